// round 13
// baseline (speedup 1.0000x reference)
#include <cuda_runtime.h>
#include <stdint.h>

// adjacency_full[i, neighbor_indices[i, j]] = adjacency_values[i, j]
// N = 8192, K = 64. Output: N*N fp32 (256 MB).
//
// Final form (R9 refined). One CTA per row:
//   0) prefetch the row's 64 (col,val) pairs into registers   [hidden]
//   1) zero the 32KB smem row (STS.128)
//   2) scatter the 64 values into smem
//   3) fence.proxy.async; elected thread issues ONE 32KB cp.async.bulk
//      (smem -> gmem, bypasses the LSU/L1 write path), then waits so smem
//      stays alive until the TMA has consumed it.
// Measured at ~6.3 TB/s effective write rate = DRAM pure-write drain ceiling
// (STG.128/STG.256/16KB-TMA/32KB-TMA all converge here; issue% ~5).

#define N_PATCHES 8192
#define K_NEIGH   64
#define THREADS   128
#define ROW_BYTES (N_PATCHES * 4)          // 32 KB
#define ROW_V4    (N_PATCHES / 4)          // 2048 float4
#define PER_THR   (ROW_V4 / THREADS)       // 16 float4 per thread

__global__ void __launch_bounds__(THREADS)
tma_row_final_kernel(const float* __restrict__ vals,
                     const int*   __restrict__ idx,
                     float* __restrict__ out)
{
    __shared__ __align__(128) float row[N_PATCHES];   // 32 KB
    const int r   = blockIdx.x;
    const int tid = threadIdx.x;

    // Phase 0: prefetch scatter operands (latency hides under the zero-fill).
    int   c = 0;
    float v = 0.f;
    if (tid < K_NEIGH) {
        int t = r * K_NEIGH + tid;
        c = idx[t];        // coalesced
        v = vals[t];       // coalesced
    }

    // Phase 1: zero the smem row (16 x STS.128 per thread).
    float4* row4 = reinterpret_cast<float4*>(row);
    const float4 z4 = make_float4(0.f, 0.f, 0.f, 0.f);
    #pragma unroll
    for (int j = 0; j < PER_THR; j++)
        row4[tid + j * THREADS] = z4;
    __syncthreads();

    // Phase 2: scatter the 64 values into the smem row.
    if (tid < K_NEIGH)
        row[c] = v;
    __syncthreads();

    // Phase 3: one 32KB bulk store smem -> gmem via the async proxy.
    asm volatile("fence.proxy.async.shared::cta;" ::: "memory");
    if (tid == 0) {
        uint32_t saddr;
        asm("{ .reg .u64 t; cvta.to.shared.u64 t, %1; cvt.u32.u64 %0, t; }"
            : "=r"(saddr) : "l"(row));
        float* dst = out + (size_t)r * N_PATCHES;
        asm volatile(
            "cp.async.bulk.global.shared::cta.bulk_group [%0], [%1], %2;"
            :: "l"(dst), "r"(saddr), "n"(ROW_BYTES) : "memory");
        asm volatile("cp.async.bulk.commit_group;" ::: "memory");
        // smem must remain allocated until the bulk store has read it.
        asm volatile("cp.async.bulk.wait_group 0;" ::: "memory");
    }
}

extern "C" void kernel_launch(void* const* d_in, const int* in_sizes, int n_in,
                              void* d_out, int out_size)
{
    const float* vals = (const float*)d_in[0];   // [N, K] float32
    const int*   idx  = (const int*)  d_in[1];   // [N, K] int32
    float* out = (float*)d_out;                  // [N, N] float32

    tma_row_final_kernel<<<N_PATCHES, THREADS, 0, 0>>>(vals, idx, out);
}